// round 1
// baseline (speedup 1.0000x reference)
#include <cuda_runtime.h>
#include <cuda_bf16.h>

// Problem constants
#define BATCH   8
#define NNODES  1024
#define IN_DIM  256
#define OUT_DIM 256
#define HEADS   8
#define HDIM    32          // OUT_DIM / HEADS
#define ROWS    (BATCH * NNODES)   // 8192

// Scratch (device globals: allocation-free)
__device__ float g_inputs[ROWS * OUT_DIM];          // [B,N,H,D] = X @ W
__device__ float g_self [BATCH * HEADS * NNODES];   // [B,H,N]
__device__ float g_neigh[BATCH * HEADS * NNODES];   // [B,H,N]

// ---------------- packed f32x2 helpers ----------------
__device__ __forceinline__ unsigned long long pack2(float lo, float hi) {
    unsigned long long r;
    asm("mov.b64 %0, {%1, %2};" : "=l"(r) : "f"(lo), "f"(hi));
    return r;
}
__device__ __forceinline__ void unpack2(unsigned long long v, float& lo, float& hi) {
    asm("mov.b64 {%0, %1}, %2;" : "=f"(lo), "=f"(hi) : "l"(v));
}
__device__ __forceinline__ unsigned long long fma2(unsigned long long a,
                                                   unsigned long long b,
                                                   unsigned long long c) {
    unsigned long long d;
    asm("fma.rn.f32x2 %0, %1, %2, %3;" : "=l"(d) : "l"(a), "l"(b), "l"(c));
    return d;
}

// ---------------- Kernel 1: inputs = X @ W  (fp32, f32x2-packed FMA) ----------------
// M=8192, N=256, K=256. BM=64, BN=64, BK=32, 256 threads, 4x4 per thread.
#define BM 64
#define BN 64
#define BK 32

__global__ __launch_bounds__(256)
void gemm_kernel(const float* __restrict__ X, const float* __restrict__ W,
                 float* __restrict__ out) {
    __shared__ __align__(16) float As[BK][BM + 4];  // stored transposed [k][m], pad=4 (conflict-free + 16B align)
    __shared__ __align__(16) float Bs[BK][BN + 4];  // [k][n]

    const int t  = threadIdx.x;
    const int n0 = blockIdx.x * BN;
    const int m0 = blockIdx.y * BM;
    const int tx = t & 15;   // col group (4 cols)
    const int ty = t >> 4;   // row group (4 rows)

    unsigned long long acc[4][2];
#pragma unroll
    for (int i = 0; i < 4; i++) { acc[i][0] = 0ull; acc[i][1] = 0ull; }

    for (int k0 = 0; k0 < IN_DIM; k0 += BK) {
        // A tile: 64 rows x 32 cols = 512 float4 slots
#pragma unroll
        for (int s = t; s < 512; s += 256) {
            int r = s >> 3;           // 0..63
            int c = (s & 7) << 2;     // 0..28
            float4 v = *(const float4*)&X[(m0 + r) * IN_DIM + k0 + c];
            As[c + 0][r] = v.x; As[c + 1][r] = v.y;
            As[c + 2][r] = v.z; As[c + 3][r] = v.w;
        }
        // B tile: 32 rows x 64 cols = 512 float4 slots
#pragma unroll
        for (int s = t; s < 512; s += 256) {
            int r = s >> 4;           // 0..31
            int c = (s & 15) << 2;    // 0..60
            *(float4*)&Bs[r][c] = *(const float4*)&W[(k0 + r) * OUT_DIM + n0 + c];
        }
        __syncthreads();

#pragma unroll
        for (int k = 0; k < BK; k++) {
            float4 a = *(const float4*)&As[k][ty * 4];
            float4 b = *(const float4*)&Bs[k][tx * 4];
            unsigned long long b01 = pack2(b.x, b.y);
            unsigned long long b23 = pack2(b.z, b.w);
            unsigned long long a2;
            a2 = pack2(a.x, a.x); acc[0][0] = fma2(a2, b01, acc[0][0]); acc[0][1] = fma2(a2, b23, acc[0][1]);
            a2 = pack2(a.y, a.y); acc[1][0] = fma2(a2, b01, acc[1][0]); acc[1][1] = fma2(a2, b23, acc[1][1]);
            a2 = pack2(a.z, a.z); acc[2][0] = fma2(a2, b01, acc[2][0]); acc[2][1] = fma2(a2, b23, acc[2][1]);
            a2 = pack2(a.w, a.w); acc[3][0] = fma2(a2, b01, acc[3][0]); acc[3][1] = fma2(a2, b23, acc[3][1]);
        }
        __syncthreads();
    }

#pragma unroll
    for (int i = 0; i < 4; i++) {
        int row = m0 + ty * 4 + i;
        float4 o;
        unpack2(acc[i][0], o.x, o.y);
        unpack2(acc[i][1], o.z, o.w);
        *(float4*)&out[row * OUT_DIM + n0 + tx * 4] = o;
    }
}

// ---------------- Kernel 2: attention score projections ----------------
// self_s[b,h,n] = dot(inputs[b,n,h,:], fc1[h,:]);  neigh_s likewise with fc2.
__global__ __launch_bounds__(256)
void scores_kernel(const float* __restrict__ inp,
                   const float* __restrict__ fc1, const float* __restrict__ fc2,
                   float* __restrict__ self_s, float* __restrict__ neigh_s) {
    const int bn = blockIdx.x;           // 0..8191
    const int t  = threadIdx.x;          // 0..255
    const int h  = t >> 5;
    const int d  = t & 31;
    float v  = inp[bn * OUT_DIM + t];
    float s1 = v * fc1[h * HDIM + d];
    float s2 = v * fc2[h * HDIM + d];
#pragma unroll
    for (int o = 16; o > 0; o >>= 1) {
        s1 += __shfl_xor_sync(0xffffffffu, s1, o);
        s2 += __shfl_xor_sync(0xffffffffu, s2, o);
    }
    if (d == 0) {
        int b = bn >> 10, n = bn & 1023;
        self_s [(b * HEADS + h) * NNODES + n] = s1;
        neigh_s[(b * HEADS + h) * NNODES + n] = s2;
    }
}

// ---------------- Kernel 3: sparse softmax + aggregation + relu ----------------
// One block per (b, n) destination row. exp(-1e9) underflows to 0 in fp32, so the
// dense-masked softmax is exactly the softmax over A's nonzeros (self-loop present).
__global__ __launch_bounds__(256)
void attn_kernel(const float* __restrict__ A,
                 const float* __restrict__ inp,
                 const float* __restrict__ self_s, const float* __restrict__ neigh_s,
                 float* __restrict__ out) {
    __shared__ float sc[NNODES * HEADS];     // 32 KB: exp-scores [j][h]
    __shared__ int   nbr[NNODES];            // neighbor indices
    __shared__ float s_self[HEADS];
    __shared__ float s_inv[HEADS];
    __shared__ int   s_cnt;

    const int blk = blockIdx.x;
    const int b = blk >> 10;
    const int n = blk & 1023;
    const int t = threadIdx.x;

    if (t == 0) s_cnt = 0;
    if (t < HEADS) s_self[t] = self_s[(b * HEADS + t) * NNODES + n];
    __syncthreads();

    // Phase 1: compact nonzero columns of A[b,n,:]
    {
        const float4 v = ((const float4*)(A + ((long)blk) * NNODES))[t];
        int idx[4]; int c = 0;
        if (v.x != 0.0f) idx[c++] = 4 * t + 0;
        if (v.y != 0.0f) idx[c++] = 4 * t + 1;
        if (v.z != 0.0f) idx[c++] = 4 * t + 2;
        if (v.w != 0.0f) idx[c++] = 4 * t + 3;
        if (c) {
            int p = atomicAdd(&s_cnt, c);
            for (int i = 0; i < c; i++) nbr[p + i] = idx[i];
        }
    }
    __syncthreads();
    const int M = s_cnt;

    // Phase 2a: raw scores sc[j][h] = leaky_relu(self + neigh_j)
    const float* nb = neigh_s + b * HEADS * NNODES;
    for (int idx = t; idx < M * HEADS; idx += 256) {
        int j = idx >> 3, h = idx & 7;
        float s = s_self[h] + nb[h * NNODES + nbr[j]];
        s = (s > 0.0f) ? s : 0.01f * s;
        sc[j * HEADS + h] = s;
    }
    __syncthreads();

    // Phase 2b: per-head max + exp + sum (warp w owns head w)
    {
        const int w = t >> 5, lane = t & 31;
        if (w < HEADS) {
            float mx = -1e30f;
            for (int j = lane; j < M; j += 32) mx = fmaxf(mx, sc[j * HEADS + w]);
#pragma unroll
            for (int o = 16; o > 0; o >>= 1) mx = fmaxf(mx, __shfl_xor_sync(0xffffffffu, mx, o));
            float sum = 0.0f;
            for (int j = lane; j < M; j += 32) {
                float e = __expf(sc[j * HEADS + w] - mx);
                sc[j * HEADS + w] = e;
                sum += e;
            }
#pragma unroll
            for (int o = 16; o > 0; o >>= 1) sum += __shfl_xor_sync(0xffffffffu, sum, o);
            if (lane == 0) s_inv[w] = 1.0f / sum;
        }
    }
    __syncthreads();

    // Phase 3: gather-aggregate. thread t = (h,d); coalesced 1KB row reads (L2-resident)
    {
        const int h = t >> 5;
        const float* inpb = inp + (long)b * NNODES * OUT_DIM;
        float a0 = 0.f, a1 = 0.f, a2 = 0.f, a3 = 0.f;
        int j = 0;
        for (; j + 4 <= M; j += 4) {
            int j0 = nbr[j + 0], j1 = nbr[j + 1], j2 = nbr[j + 2], j3 = nbr[j + 3];
            float w0 = sc[(j + 0) * HEADS + h], w1 = sc[(j + 1) * HEADS + h];
            float w2 = sc[(j + 2) * HEADS + h], w3 = sc[(j + 3) * HEADS + h];
            a0 += w0 * inpb[j0 * OUT_DIM + t];
            a1 += w1 * inpb[j1 * OUT_DIM + t];
            a2 += w2 * inpb[j2 * OUT_DIM + t];
            a3 += w3 * inpb[j3 * OUT_DIM + t];
        }
        for (; j < M; j++) {
            a0 += sc[j * HEADS + h] * inpb[nbr[j] * OUT_DIM + t];
        }
        float acc = (a0 + a1) + (a2 + a3);
        out[(long)blk * OUT_DIM + t] = fmaxf(acc * s_inv[h], 0.0f);
    }
}

// ---------------- launch ----------------
extern "C" void kernel_launch(void* const* d_in, const int* in_sizes, int n_in,
                              void* d_out, int out_size) {
    const float* A   = (const float*)d_in[0];   // [B,N,N]
    const float* X   = (const float*)d_in[1];   // [B,N,IN_DIM]
    const float* W   = (const float*)d_in[2];   // [IN_DIM,OUT_DIM]
    const float* fc1 = (const float*)d_in[3];   // [H,D]
    const float* fc2 = (const float*)d_in[4];   // [H,D]
    float* out = (float*)d_out;                 // [B,N,OUT_DIM]

    float* inp;     cudaGetSymbolAddress((void**)&inp,   g_inputs);
    float* self_s;  cudaGetSymbolAddress((void**)&self_s, g_self);
    float* neigh_s; cudaGetSymbolAddress((void**)&neigh_s, g_neigh);

    dim3 ggrid(OUT_DIM / BN, ROWS / BM);        // (4, 128)
    gemm_kernel<<<ggrid, 256>>>(X, W, inp);
    scores_kernel<<<ROWS, 256>>>(inp, fc1, fc2, self_s, neigh_s);
    attn_kernel<<<ROWS, 256>>>(A, inp, self_s, neigh_s, out);
}